// round 4
// baseline (speedup 1.0000x reference)
#include <cuda_runtime.h>

// QuantizedCodebook (VQ-VAE): N=131072 rows, D=64, K=512.
// out layout (confirmed): [loss(1) | quantize(N*D) | indices(N)] fp32.
// Register-tiled outer product: thread tile = 8 rows x 16 codes (8 f32x2 pairs).

#define KCODES 512
#define DDIM   64
#define TPB    256
#define TROWS  8            // rows per thread (per warp)
#define TPAIRS 8            // code-pairs per thread (lane covers pairs lane+32m)
#define TILE_R 64           // rows per block tile (8 warps * 8 rows)
#define MAXBLK 512

typedef unsigned long long ull;

__device__ double   g_partials[MAXBLK];
__device__ unsigned g_done;   // zero-init; last block resets each run

__device__ __forceinline__ ull f32x2_dup(float v) {
    ull r; asm("mov.b64 %0, {%1, %1};" : "=l"(r) : "f"(v)); return r;
}
__device__ __forceinline__ ull ffma2(ull a, ull b, ull c) {
    ull d; asm("fma.rn.f32x2 %0, %1, %2, %3;" : "=l"(d) : "l"(a), "l"(b), "l"(c));
    return d;
}
__device__ __forceinline__ float2 as_float2(ull a) {
    float2 f; asm("mov.b64 {%0, %1}, %2;" : "=f"(f.x), "=f"(f.y) : "l"(a));
    return f;
}

__global__ void __launch_bounds__(TPB, 1)
vq_kernel(const float* __restrict__ x, const float* __restrict__ cb,
          float* __restrict__ out, int nrows)
{
    // smem: cbTf[64][512] dim-major (128KB) | xd[64][64] dup'd rows (32KB) | scq[512]
    extern __shared__ unsigned char smem_raw[];
    float* cbTf = (float*)smem_raw;                          // [i*512 + c]
    ull*   xd   = (ull*)(smem_raw + KCODES * DDIM * 4);      // [r*64 + i] = {x,x}
    float* scq  = (float*)(smem_raw + KCODES * DDIM * 4 + TILE_R * DDIM * 8);

    float* out_q   = out + 1;
    float* out_idx = out + 1 + (size_t)nrows * DDIM;

    const int tid  = threadIdx.x;
    const int w    = tid >> 5;
    const int lane = tid & 31;

    // ---- One-time staging: transpose codebook to dim-major; ||c||^2 ----
    // read cb[c*64+i] (uncoalesced, L2-cached), write cbTf[i*512+c] coalesced.
    for (int idx = tid; idx < KCODES * DDIM; idx += TPB) {
        int i = idx >> 9;          // dim
        int c = idx & (KCODES - 1);
        cbTf[idx] = cb[c * DDIM + i];
    }
    for (int c = tid; c < KCODES; c += TPB) {
        const float* cr = cb + c * DDIM;
        float s = 0.f;
        #pragma unroll
        for (int i = 0; i < DDIM; i++) s = fmaf(cr[i], cr[i], s);
        scq[c] = s;
    }
    __syncthreads();

    const ull*    cbp = (const ull*)cbTf;          // [i*256 + pair]
    const float2* scq2 = (const float2*)scq;       // [pair] = {||c_2p||^2, ||c_2p+1||^2}

    const int ntiles = nrows / TILE_R;             // 2048
    float lsum = 0.f;

    for (int t = blockIdx.x; t < ntiles; t += gridDim.x) {
        // ---- Stage row tile, duplicated {x,x} ----
        const float4* xsrc =
            reinterpret_cast<const float4*>(x + (size_t)t * TILE_R * DDIM);
        for (int idx = tid; idx < TILE_R * (DDIM / 4); idx += TPB) {
            float4 v = xsrc[idx];
            ull* dst = xd + idx * 4;
            dst[0] = f32x2_dup(v.x);
            dst[1] = f32x2_dup(v.y);
            dst[2] = f32x2_dup(v.z);
            dst[3] = f32x2_dup(v.w);
        }
        __syncthreads();

        // ---- Main loop: a[r][m] accumulates dots for (row w*8+r, codes 2p,2p+1)
        const ull* xdr = xd + (w * TROWS) * DDIM;

        ull a[TROWS][TPAIRS];
        #pragma unroll
        for (int r = 0; r < TROWS; r++)
            #pragma unroll
            for (int m = 0; m < TPAIRS; m++) a[r][m] = 0ull;

        #pragma unroll 2
        for (int i = 0; i < DDIM; i++) {
            ull cc[TPAIRS];
            const ull* cbi = cbp + i * (KCODES / 2) + lane;
            #pragma unroll
            for (int m = 0; m < TPAIRS; m++) cc[m] = cbi[32 * m];
            #pragma unroll
            for (int r = 0; r < TROWS; r++) {
                ull xr = xdr[r * DDIM + i];
                #pragma unroll
                for (int m = 0; m < TPAIRS; m++)
                    a[r][m] = ffma2(xr, cc[m], a[r][m]);
            }
        }

        // ---- Per-row argmin (warp covers all 512 codes) + epilogue ----
        #pragma unroll 1
        for (int r = 0; r < TROWS; r++) {
            int grow = t * TILE_R + w * TROWS + r;

            float best = 3.402823466e38f;
            int   bi   = 0;
            #pragma unroll
            for (int m = 0; m < TPAIRS; m++) {
                int p = lane + 32 * m;
                float2 dot = as_float2(a[r][m]);
                float2 q   = scq2[p];
                float s0 = fmaf(-2.f, dot.x, q.x);
                float s1 = fmaf(-2.f, dot.y, q.y);
                if (s0 < best) { best = s0; bi = 2 * p; }
                if (s1 < best) { best = s1; bi = 2 * p + 1; }
            }
            // warp min-reduce with first-index tie-break
            #pragma unroll
            for (int off = 16; off; off >>= 1) {
                float ob = __shfl_xor_sync(0xffffffffu, best, off);
                int   oi = __shfl_xor_sync(0xffffffffu, bi, off);
                if (ob < best || (ob == best && oi < bi)) { best = ob; bi = oi; }
            }

            if (lane == 0) out_idx[grow] = (float)bi;

            // quantize + loss: 2 dims per lane, q = x + (c - x)
            const float2* xr2 =
                reinterpret_cast<const float2*>(x + (size_t)grow * DDIM) + lane;
            const float2* cr2 =
                reinterpret_cast<const float2*>(cb + (size_t)bi * DDIM) + lane;
            float2 xv = *xr2;
            float2 cv = *cr2;
            float o0 = xv.x + (cv.x - xv.x);
            float o1 = xv.y + (cv.y - xv.y);
            float t0 = o0 - xv.x; lsum = fmaf(t0, t0, lsum);
            float t1 = o1 - xv.y; lsum = fmaf(t1, t1, lsum);
            float* oq = out_q + (size_t)grow * DDIM + 2 * lane;
            oq[0] = o0;   // out_q only 4B-aligned: scalar stores
            oq[1] = o1;
        }
        __syncthreads();   // protect xd before next tile restage
    }

    // ---- Loss: block reduce -> double partial; last block finalizes ----
    __shared__ float warp_sums[TPB / 32];
    #pragma unroll
    for (int off = 16; off; off >>= 1)
        lsum += __shfl_down_sync(0xffffffffu, lsum, off);
    if (lane == 0) warp_sums[w] = lsum;
    __syncthreads();
    if (tid == 0) {
        float b = 0.f;
        #pragma unroll
        for (int i = 0; i < TPB / 32; i++) b += warp_sums[i];
        g_partials[blockIdx.x] = (double)b;
        __threadfence();
        unsigned done = atomicAdd(&g_done, 1u);
        if (done == gridDim.x - 1) {
            double total = 0.0;
            for (int k = 0; k < gridDim.x; k++) total += g_partials[k];
            out[0] = (float)(total * 1.25 / ((double)nrows * DDIM));
            __threadfence();
            g_done = 0;   // self-reset for graph replay
        }
    }
}

extern "C" void kernel_launch(void* const* d_in, const int* in_sizes, int n_in,
                              void* d_out, int out_size)
{
    const float* x  = (const float*)d_in[0];   // inputs  [128,32,32,64]
    const float* cb = (const float*)d_in[1];   // codebook [512,64]
    const int n_elem = in_sizes[0];            // 8388608
    const int nrows  = n_elem / DDIM;          // 131072

    const int smem_bytes = KCODES * DDIM * 4      // cbTf 128KB
                         + TILE_R * DDIM * 8      // xd    32KB
                         + KCODES * 4;            // scq    2KB
    cudaFuncSetAttribute(vq_kernel,
                         cudaFuncAttributeMaxDynamicSharedMemorySize, smem_bytes);

    int sms = 148;
    cudaDeviceGetAttribute(&sms, cudaDevAttrMultiProcessorCount, 0);
    if (sms > MAXBLK) sms = MAXBLK;

    vq_kernel<<<sms, TPB, smem_bytes>>>(x, cb, (float*)d_out, nrows);
}